// round 9
// baseline (speedup 1.0000x reference)
#include <cuda_runtime.h>
#include <cuda_bf16.h>
#include <cstdint>

// ---------------------------------------------------------------- constants
#define N_ANCH   8192
#define DIM      64
#define JSPLIT   8
#define STRIPS   64            // 8192 / 128
#define BM       128
#define BN       64
#define CHUNKS   16            // 1024 / 64 per split
#define KSTEPS   4             // K = 64 (hi only)
#define THREADS  256
#define ROWB     144           // 64*2 + 16 pad (conflict-free ldmatrix)
#define MARGIN_F 0.5f

// SMEM layout (per CTA): A 18432 | B x3 9216 | meta x3 512
#define OFF_A     0
#define OFF_B     18432
#define BSTRIDE   9216
#define OFF_META  46080
#define MSTRIDE   512
#define SMEM_TOTAL 47616

struct __align__(8) Meta { float sq; int tgt; };

// ---------------------------------------------------------------- scratch
__device__ unsigned int g_ebf[N_ANCH * 32];   // bf16 hi pairs, 128B per row
__device__ Meta  g_meta[N_ANCH];
__device__ float g_maxval[JSPLIT * N_ANCH];
__device__ int   g_maxidx[JSPLIT * N_ANCH];
__device__ float g_minval[JSPLIT * N_ANCH];
__device__ int   g_minidx[JSPLIT * N_ANCH];
__device__ float g_strip_loss[STRIPS];
__device__ unsigned int g_strip_cnt[STRIPS];
__device__ unsigned int g_done_cnt;

// ---------------------------------------------------------------- PTX helpers
__device__ __forceinline__ uint32_t smem_u32(const void* p) {
    uint32_t a;
    asm("{ .reg .u64 t; cvta.to.shared.u64 t, %1; cvt.u32.u64 %0, t; }"
        : "=r"(a) : "l"(p));
    return a;
}
#define CP16(d, s) \
    asm volatile("cp.async.cg.shared.global [%0], [%1], 16;" \
                 :: "r"(d), "l"(s) : "memory")
#define CP_COMMIT() asm volatile("cp.async.commit_group;" ::: "memory")
#define CP_WAIT1()  asm volatile("cp.async.wait_group 1;" ::: "memory")

#define LDSM_X4(R, addr) \
    asm volatile("ldmatrix.sync.aligned.m8n8.x4.shared.b16 {%0,%1,%2,%3}, [%4];" \
                 : "=r"((R)[0]), "=r"((R)[1]), "=r"((R)[2]), "=r"((R)[3]) \
                 : "r"(addr))

#define MMA16816(D, A, B0, B1) \
    asm volatile("mma.sync.aligned.m16n8k16.row.col.f32.bf16.bf16.f32 " \
                 "{%0,%1,%2,%3},{%4,%5,%6,%7},{%8,%9},{%0,%1,%2,%3};" \
                 : "+f"((D)[0]), "+f"((D)[1]), "+f"((D)[2]), "+f"((D)[3]) \
                 : "r"((A)[0]), "r"((A)[1]), "r"((A)[2]), "r"((A)[3]), \
                   "r"(B0), "r"(B1))

// ---------------------------------------------------------------- kernel 0: prep
__global__ void prep_kernel(const float* __restrict__ emb,
                            const int* __restrict__ tgt) {
    if (blockIdx.x == 0) {
        if (threadIdx.x < STRIPS) g_strip_cnt[threadIdx.x] = 0;
        if (threadIdx.x == STRIPS) g_done_cnt = 0;
    }
    int idx = blockIdx.x * blockDim.x + threadIdx.x;
    int row = idx >> 3, sub = idx & 7;
    const float4* src = reinterpret_cast<const float4*>(emb);
    float4 v0 = src[row * 16 + sub * 2];
    float4 v1 = src[row * 16 + sub * 2 + 1];

    unsigned int h[4];
    h[0] = ((unsigned)__bfloat16_as_ushort(__float2bfloat16(v0.y)) << 16) |
            (unsigned)__bfloat16_as_ushort(__float2bfloat16(v0.x));
    h[1] = ((unsigned)__bfloat16_as_ushort(__float2bfloat16(v0.w)) << 16) |
            (unsigned)__bfloat16_as_ushort(__float2bfloat16(v0.z));
    h[2] = ((unsigned)__bfloat16_as_ushort(__float2bfloat16(v1.y)) << 16) |
            (unsigned)__bfloat16_as_ushort(__float2bfloat16(v1.x));
    h[3] = ((unsigned)__bfloat16_as_ushort(__float2bfloat16(v1.w)) << 16) |
            (unsigned)__bfloat16_as_ushort(__float2bfloat16(v1.z));
    reinterpret_cast<uint4*>(g_ebf)[row * 8 + sub] =
        make_uint4(h[0], h[1], h[2], h[3]);

    float s = v0.x * v0.x + v0.y * v0.y + v0.z * v0.z + v0.w * v0.w +
              v1.x * v1.x + v1.y * v1.y + v1.z * v1.z + v1.w * v1.w;
    s += __shfl_xor_sync(0xFFFFFFFFu, s, 1);
    s += __shfl_xor_sync(0xFFFFFFFFu, s, 2);
    s += __shfl_xor_sync(0xFFFFFFFFu, s, 4);
    if (sub == 0) { Meta m; m.sq = s; m.tgt = tgt[row]; g_meta[row] = m; }
}

// A tile: 128 rows x 128B (hi). B tile: 64 rows x 128B.
__device__ __forceinline__ void fill_a(uint32_t dst_sb, int row0, int tid) {
    const char* src = reinterpret_cast<const char*>(g_ebf);
#pragma unroll
    for (int k = 0; k < 4; k++) {
        int idx = tid + k * THREADS;
        int r = idx >> 3, c8 = idx & 7;
        CP16(dst_sb + r * ROWB + c8 * 16,
             src + (size_t)(row0 + r) * 128 + c8 * 16);
    }
}
__device__ __forceinline__ void fill_b(uint32_t dst_sb, int row0, int tid) {
    const char* src = reinterpret_cast<const char*>(g_ebf);
#pragma unroll
    for (int k = 0; k < 2; k++) {
        int idx = tid + k * THREADS;
        int r = idx >> 3, c8 = idx & 7;
        CP16(dst_sb + r * ROWB + c8 * 16,
             src + (size_t)(row0 + r) * 128 + c8 * 16);
    }
}

// ---------------------------------------------------------------- kernel 1: mining + fused loss
__global__ __launch_bounds__(THREADS, 2)
void mine_kernel(const int* __restrict__ tgt,
                 const float* __restrict__ emb,
                 float* __restrict__ out) {
    extern __shared__ char smem[];
    __shared__ unsigned int s_last, s_fin;
    const uint32_t sb = smem_u32(smem);
    const int tid = threadIdx.x, wid = tid >> 5, lane = tid & 31;
    const int wm = wid >> 1, wn = wid & 1;       // 4 x 2 warp grid
    const int m_warp = wm * 32, n_warp = wn * 32;
    const int strip = blockIdx.x, split = blockIdx.y;
    const int i0 = strip * BM;
    const int j0 = split * (N_ANCH / JSPLIT);

    // Prologue: G0 = A + B(buf0), G1 = B(buf1)
    fill_a(sb + OFF_A, i0, tid);
    fill_b(sb + OFF_B, j0, tid);
    if (tid < BN)
        reinterpret_cast<Meta*>(smem + OFF_META)[tid] = g_meta[j0 + tid];
    CP_COMMIT();
    fill_b(sb + OFF_B + BSTRIDE, j0 + BN, tid);
    if (tid < BN)
        reinterpret_cast<Meta*>(smem + OFF_META + MSTRIDE)[tid] =
            g_meta[j0 + BN + tid];
    CP_COMMIT();

    int tslot[4];
#pragma unroll
    for (int mt = 0; mt < 2; mt++)
#pragma unroll
        for (int h = 0; h < 2; h++)
            tslot[mt * 2 + h] = tgt[i0 + m_warp + mt * 16 + (lane >> 2) + h * 8];

    const float INF_F = __int_as_float(0x7f800000);
    float mxv[4], mnv[4];
    int   mxj[4], mnj[4];
#pragma unroll
    for (int s = 0; s < 4; s++) {
        mxv[s] = -INF_F; mnv[s] = INF_F; mxj[s] = 0; mnj[s] = 0;
    }

    const uint32_t lmoff = (uint32_t)(lane & 15) * ROWB + ((lane & 16) ? 16 : 0);
    const uint32_t aA = sb + OFF_A + m_warp * ROWB + lmoff;

    CP_WAIT1();
    __syncthreads();
    uint32_t Af[2][KSTEPS][4];
#pragma unroll
    for (int mt = 0; mt < 2; mt++)
#pragma unroll
        for (int s = 0; s < KSTEPS; s++)
            LDSM_X4(Af[mt][s], aA + mt * (16 * ROWB) + s * 32);

    for (int t = 0; t < CHUNKS; t++) {
        const int buf = t % 3;
        if (t > 0) { CP_WAIT1(); __syncthreads(); }

        const uint32_t aB = sb + OFF_B + buf * BSTRIDE + n_warp * ROWB + lmoff;
        const Meta* meta =
            reinterpret_cast<const Meta*>(smem + OFF_META + buf * MSTRIDE);

        float d[2][4][4];
#pragma unroll
        for (int mt = 0; mt < 2; mt++)
#pragma unroll
            for (int nt = 0; nt < 4; nt++)
#pragma unroll
                for (int e = 0; e < 4; e++) d[mt][nt][e] = 0.f;

#pragma unroll
        for (int s = 0; s < KSTEPS; s++) {
            uint32_t Bf[2][4];
#pragma unroll
            for (int np = 0; np < 2; np++)
                LDSM_X4(Bf[np], aB + np * (16 * ROWB) + s * 32);
#pragma unroll
            for (int mt = 0; mt < 2; mt++)
#pragma unroll
                for (int nt = 0; nt < 4; nt++) {
                    int np = nt >> 1, sel = nt & 1;
                    MMA16816(d[mt][nt], Af[mt][s], Bf[np][sel], Bf[np][2 + sel]);
                }
        }

        const int jb = j0 + t * BN;
        if (t + 2 < CHUNKS) {
            const int nb = (t + 2) % 3;
            fill_b(sb + OFF_B + nb * BSTRIDE, jb + 2 * BN, tid);
            if (tid < BN)
                reinterpret_cast<Meta*>(smem + OFF_META + nb * MSTRIDE)[tid] =
                    g_meta[jb + 2 * BN + tid];
            CP_COMMIT();
        }

#pragma unroll
        for (int nt = 0; nt < 4; nt++)
#pragma unroll
            for (int c = 0; c < 2; c++) {
                int jl = n_warp + nt * 8 + (lane & 3) * 2 + c;
                int j = jb + jl;
                Meta m = meta[jl];
#pragma unroll
                for (int mt = 0; mt < 2; mt++)
#pragma unroll
                    for (int h = 0; h < 2; h++) {
                        int sl = mt * 2 + h;
                        float key = fmaf(-2.0f, d[mt][nt][h * 2 + c], m.sq);
                        bool same = (m.tgt == tslot[sl]);
                        bool cp = same && (key > mxv[sl]);
                        mxv[sl] = cp ? key : mxv[sl];
                        mxj[sl] = cp ? j : mxj[sl];
                        bool cn = (!same) && (key < mnv[sl]);
                        mnv[sl] = cn ? key : mnv[sl];
                        mnj[sl] = cn ? j : mnj[sl];
                    }
            }
    }

    // Quad reduce (same rows, different j)
#pragma unroll
    for (int s = 0; s < 4; s++) {
#pragma unroll
        for (int off = 1; off <= 2; off <<= 1) {
            float ov = __shfl_xor_sync(0xFFFFFFFFu, mxv[s], off);
            int   oj = __shfl_xor_sync(0xFFFFFFFFu, mxj[s], off);
            if (ov > mxv[s] || (ov == mxv[s] && oj < mxj[s])) {
                mxv[s] = ov; mxj[s] = oj;
            }
            ov = __shfl_xor_sync(0xFFFFFFFFu, mnv[s], off);
            oj = __shfl_xor_sync(0xFFFFFFFFu, mnj[s], off);
            if (ov < mnv[s] || (ov == mnv[s] && oj < mnj[s])) {
                mnv[s] = ov; mnj[s] = oj;
            }
        }
    }

    // Cross-warp combine through smem, write this split's results
    float* s_mv = reinterpret_cast<float*>(smem + OFF_B);
    int*   s_mj = reinterpret_cast<int*>(smem + OFF_B + 1024);
    float* s_nv = reinterpret_cast<float*>(smem + OFF_B + 2048);
    int*   s_nj = reinterpret_cast<int*>(smem + OFF_B + 3072);
    __syncthreads();
    if ((lane & 3) == 0) {
#pragma unroll
        for (int mt = 0; mt < 2; mt++)
#pragma unroll
            for (int h = 0; h < 2; h++) {
                int sl = mt * 2 + h;
                int row = m_warp + mt * 16 + (lane >> 2) + h * 8;
                int o = wn * 128 + row;
                s_mv[o] = mxv[sl]; s_mj[o] = mxj[sl];
                s_nv[o] = mnv[sl]; s_nj[o] = mnj[sl];
            }
    }
    __syncthreads();
    if (tid < 128) {
        float bv = -INF_F, sv = INF_F;
        int bj = 0, sj = 0;
#pragma unroll
        for (int w = 0; w < 2; w++) {
            int o = w * 128 + tid;
            float v = s_mv[o]; int j = s_mj[o];
            if (v > bv || (v == bv && j < bj)) { bv = v; bj = j; }
            v = s_nv[o]; j = s_nj[o];
            if (v < sv || (v == sv && j < sj)) { sv = v; sj = j; }
        }
        const int oi = split * N_ANCH + i0 + tid;
        g_maxval[oi] = bv; g_maxidx[oi] = bj;
        g_minval[oi] = sv; g_minidx[oi] = sj;
    }
    __threadfence();          // publish this CTA's results (per-thread release)
    __syncthreads();

    // Per-strip ticket: last CTA of this strip computes the strip's loss.
    if (tid == 0)
        s_last = (atomicAdd(&g_strip_cnt[strip], 1u) == JSPLIT - 1) ? 1u : 0u;
    __syncthreads();
    if (!s_last) return;
    __threadfence();          // acquire side: see all splits' results

    // --- fused loss: 2 threads per anchor ---
    float* red = reinterpret_cast<float*>(smem + OFF_B + 4096);
    {
        const int a = tid >> 1, sub = tid & 1;
        const int i = i0 + a;

        float maxv = -INF_F; int p = 0;
        float minv =  INF_F; int n = 0;
#pragma unroll
        for (int s = 0; s < JSPLIT; s++) {
            const int o = s * N_ANCH + i;
            float v = g_maxval[o];
            if (v > maxv) { maxv = v; p = g_maxidx[o]; }
            v = g_minval[o];
            if (v < minv) { minv = v; n = g_minidx[o]; }
        }

        const float4* ei = reinterpret_cast<const float4*>(emb + (size_t)i * DIM) + sub * 8;
        const float4* ep = reinterpret_cast<const float4*>(emb + (size_t)p * DIM) + sub * 8;
        const float4* en = reinterpret_cast<const float4*>(emb + (size_t)n * DIM) + sub * 8;
        float ap = 0.f, an = 0.f;
#pragma unroll
        for (int k = 0; k < 8; k++) {
            float4 vi = ei[k], vp = ep[k], vn = en[k];
            float dx;
            dx = vi.x - vp.x; ap += dx * dx;
            dx = vi.y - vp.y; ap += dx * dx;
            dx = vi.z - vp.z; ap += dx * dx;
            dx = vi.w - vp.w; ap += dx * dx;
            dx = vi.x - vn.x; an += dx * dx;
            dx = vi.y - vn.y; an += dx * dx;
            dx = vi.z - vn.z; an += dx * dx;
            dx = vi.w - vn.w; an += dx * dx;
        }
        float v = ap - an;
        v += __shfl_xor_sync(0xFFFFFFFFu, v, 1);
        if (sub == 0) red[a] = fmaxf(v + MARGIN_F, 0.0f);
    }
    __syncthreads();
#pragma unroll
    for (int off = 64; off > 0; off >>= 1) {
        if (tid < off) red[tid] += red[tid + off];
        __syncthreads();
    }
    if (tid == 0) {
        g_strip_loss[strip] = red[0];
        __threadfence();
        s_fin = (atomicAdd(&g_done_cnt, 1u) == STRIPS - 1) ? 1u : 0u;
    }
    __syncthreads();
    if (!s_fin) return;
    __threadfence();

    // Globally last CTA: fixed-order tree sum over strips -> mean
    if (tid < STRIPS) red[tid] = g_strip_loss[tid];
    __syncthreads();
#pragma unroll
    for (int off = 32; off > 0; off >>= 1) {
        if (tid < off) red[tid] += red[tid + off];
        __syncthreads();
    }
    if (tid == 0) out[0] = red[0] / (float)N_ANCH;
}

// ----------------------------------------------------------------
extern "C" void kernel_launch(void* const* d_in, const int* in_sizes, int n_in,
                              void* d_out, int out_size) {
    const float* emb = (const float*)d_in[0];
    const int*   tgt = (const int*)d_in[1];
    float*       out = (float*)d_out;

    cudaFuncSetAttribute(mine_kernel, cudaFuncAttributeMaxDynamicSharedMemorySize,
                         SMEM_TOTAL);

    prep_kernel<<<(N_ANCH * 8) / 256, 256>>>(emb, tgt);
    dim3 grid(STRIPS, JSPLIT);
    mine_kernel<<<grid, THREADS, SMEM_TOTAL>>>(tgt, emb, out);
}